// round 14
// baseline (speedup 1.0000x reference)
#include <cuda_runtime.h>
#include <cuda_bf16.h>
#include <cuda_fp16.h>
#include <cstdint>
#include <cstddef>

#define NN    200000
#define EE    200000
#define CIN   512
#define CHID  512
#define COUT  256
#define KHOPS 10
#define CHUNK 25000     // 8 chunks: per-chunk scratch (~102 MB) stays L2-resident

// ---------------- device scratch (static; no allocation) ----------------
__device__ int           g_is64;
__device__ unsigned int  g_degi[NN];
__device__ __align__(16) float g_coef[EE];
__device__ int           g_col[EE];
__device__ int           g_idx[(size_t)KHOPS * EE];     // col^k chains
__device__ __align__(16) float g_P[(size_t)KHOPS * EE]; // cumulative coef products
__device__ __align__(16) float g_h[(size_t)NN * COUT];  // MLP output (fp32)
__device__ __align__(16) __half g_hf[(size_t)NN * COUT]; // relu(h) in fp16 (gather path)
// per-chunk split activations
__device__ __align__(16) __nv_bfloat16 g_xh[(size_t)CHUNK * CIN];
__device__ __align__(16) __nv_bfloat16 g_xl[(size_t)CHUNK * CIN];
__device__ __align__(16) __nv_bfloat16 g_t1h[(size_t)CHUNK * CHID];
__device__ __align__(16) __nv_bfloat16 g_t1l[(size_t)CHUNK * CHID];
// transposed + bf16-split weights: Wt[n][k] = W[k][n]
__device__ __align__(16) __nv_bfloat16 g_W1h[(size_t)CHID * CIN];
__device__ __align__(16) __nv_bfloat16 g_W1l[(size_t)CHID * CIN];
__device__ __align__(16) __nv_bfloat16 g_W2h[(size_t)COUT * CHID];
__device__ __align__(16) __nv_bfloat16 g_W2l[(size_t)COUT * CHID];

// ---------------- edge_index dtype detection ----------------
__global__ void k_detect(const int* __restrict__ buf) {
    __shared__ int nz;
    if (threadIdx.x == 0) nz = 0;
    __syncthreads();
    int local = 0;
    for (int i = threadIdx.x; i < 1024; i += blockDim.x)
        if (buf[2 * i + 1] != 0) local = 1;
    if (local) atomicOr(&nz, 1);
    __syncthreads();
    if (threadIdx.x == 0) g_is64 = (nz == 0) ? 1 : 0;
}
__device__ __forceinline__ int edge_row(const int* buf, int e) {
    int v = g_is64 ? buf[2 * e] : buf[e];
    unsigned u = (unsigned)v;
    return (u < NN) ? (int)u : 0;
}
__device__ __forceinline__ int edge_col(const int* buf, int e) {
    int v = g_is64 ? buf[2 * (EE + e)] : buf[EE + e];
    unsigned u = (unsigned)v;
    return (u < NN) ? (int)u : 0;
}

// ---------------- graph prep ----------------
__global__ void k_zero_deg() {
    int i = blockIdx.x * blockDim.x + threadIdx.x;
    if (i < NN) g_degi[i] = 0u;
}
__global__ void k_count(const int* __restrict__ ei) {
    int e = blockIdx.x * blockDim.x + threadIdx.x;
    if (e < EE) atomicAdd(&g_degi[edge_row(ei, e)], 1u);
}
__global__ void k_coef(const int* __restrict__ ei) {
    int e = blockIdx.x * blockDim.x + threadIdx.x;
    if (e >= EE) return;
    int r = edge_row(ei, e);
    int c = edge_col(ei, e);
    float dr = (float)g_degi[r], dc = (float)g_degi[c];
    float ir = dr > 0.f ? rsqrtf(dr) : 0.f;
    float ic = dc > 0.f ? rsqrtf(dc) : 0.f;
    g_coef[e] = ir * ic;
    g_col[e]  = c;
}

// ---------------- hop-chain precompute (single kernel, serial walk) ----------------
__global__ void k_chain() {
    int e = blockIdx.x * blockDim.x + threadIdx.x;
    if (e >= EE) return;
    int   cur = g_col[e];
    float p   = g_coef[e];
    g_idx[e] = cur;
    g_P[e]   = p;
#pragma unroll
    for (int k = 1; k < KHOPS; ++k) {
        p  *= g_coef[cur];
        cur = g_col[cur];
        g_idx[(size_t)k * EE + e] = cur;
        g_P[(size_t)k * EE + e]   = p;
    }
}

// ---------------- weight transpose + bf16 split ----------------
__global__ void k_prep_w(const float* __restrict__ W, __nv_bfloat16* __restrict__ Th,
                         __nv_bfloat16* __restrict__ Tl, int Kdim, int Ncols) {
    int i = blockIdx.x * blockDim.x + threadIdx.x;
    if (i >= Kdim * Ncols) return;
    int n = i / Kdim, k = i % Kdim;
    float v = W[(size_t)k * Ncols + n];
    __nv_bfloat16 h = __float2bfloat16_rn(v);
    Th[i] = h;
    Tl[i] = __float2bfloat16_rn(v - __bfloat162float(h));
}

// ---------------- fp32 -> bf16 hi/lo split ----------------
__global__ void k_split(const float* __restrict__ src,
                        __nv_bfloat16* __restrict__ Th,
                        __nv_bfloat16* __restrict__ Tl, int n4) {
    int i = blockIdx.x * blockDim.x + threadIdx.x;
    if (i >= n4) return;
    float4 v = ((const float4*)src)[i];
    float f[4] = {v.x, v.y, v.z, v.w};
    uint32_t h[2], l[2];
#pragma unroll
    for (int p = 0; p < 2; ++p) {
        __nv_bfloat16 h0 = __float2bfloat16_rn(f[2 * p]);
        __nv_bfloat16 h1 = __float2bfloat16_rn(f[2 * p + 1]);
        __nv_bfloat16 l0 = __float2bfloat16_rn(f[2 * p]     - __bfloat162float(h0));
        __nv_bfloat16 l1 = __float2bfloat16_rn(f[2 * p + 1] - __bfloat162float(h1));
        h[p] = ((uint32_t)__bfloat16_as_ushort(h1) << 16) | __bfloat16_as_ushort(h0);
        l[p] = ((uint32_t)__bfloat16_as_ushort(l1) << 16) | __bfloat16_as_ushort(l0);
    }
    ((uint2*)Th)[i] = make_uint2(h[0], h[1]);
    ((uint2*)Tl)[i] = make_uint2(l[0], l[1]);
}

// ---------------- warp-MMA bf16-split GEMM, cp.async double-buffered ----------------
#define RSTR     20
#define ARR_B    10240
#define STG_B    40960

__device__ __forceinline__ void cpa16(uint32_t dst, const void* src) {
    asm volatile("cp.async.cg.shared.global [%0], [%1], 16;" :: "r"(dst), "l"(src));
}
__device__ __forceinline__ void cpa_commit() {
    asm volatile("cp.async.commit_group;");
}
template<int N>
__device__ __forceinline__ void cpa_wait() {
    asm volatile("cp.async.wait_group %0;" :: "n"(N));
}
__device__ __forceinline__ void mma_bf16(float& d0, float& d1, float& d2, float& d3,
                                         uint32_t a0, uint32_t a1, uint32_t a2, uint32_t a3,
                                         uint32_t b0, uint32_t b1) {
    asm volatile(
        "mma.sync.aligned.m16n8k16.row.col.f32.bf16.bf16.f32 "
        "{%0,%1,%2,%3}, {%4,%5,%6,%7}, {%8,%9}, {%0,%1,%2,%3};"
        : "+f"(d0), "+f"(d1), "+f"(d2), "+f"(d3)
        : "r"(a0), "r"(a1), "r"(a2), "r"(a3), "r"(b0), "r"(b1));
}

__device__ __forceinline__ void stage_load(uint32_t smb, int s,
        const __nv_bfloat16* Ah, const __nv_bfloat16* Al,
        const __nv_bfloat16* Bh, const __nv_bfloat16* Bl,
        int m0, int n0, int k0, int Mrows, int Kdim, int tid)
{
    uint32_t base = smb + s * STG_B;
#pragma unroll
    for (int uu = 0; uu < 2; ++uu) {
        int u   = tid + uu * 256;
        int row = u >> 2, seg = u & 3;
        int m = m0 + row;
        if (m >= Mrows) m = Mrows - 1;
        size_t ao = (size_t)m * Kdim + k0 + seg * 8;
        size_t bo = (size_t)(n0 + row) * Kdim + k0 + seg * 8;
        uint32_t d = base + row * 80 + seg * 16;
        cpa16(d,             Ah + ao);
        cpa16(d + ARR_B,     Al + ao);
        cpa16(d + 2 * ARR_B, Bh + bo);
        cpa16(d + 3 * ARR_B, Bl + bo);
    }
}

__device__ __forceinline__ void compute_stage(const uint32_t* sAh, const uint32_t* sAl,
        const uint32_t* sBh, const uint32_t* sBl,
        int wm, int wn, int lane, float acc[4][4][4])
{
#pragma unroll
    for (int ks = 0; ks < 2; ++ks) {
        const int kp = ks * 8 + (lane & 3);
        uint32_t ah[4][4], bh[4][2], bl[4][2], al[4][4];
#pragma unroll
        for (int i = 0; i < 4; ++i) {
            int r = (wm * 64 + i * 16 + (lane >> 2)) * RSTR + kp;
            ah[i][0] = sAh[r];
            ah[i][1] = sAh[r + 8 * RSTR];
            ah[i][2] = sAh[r + 4];
            ah[i][3] = sAh[r + 8 * RSTR + 4];
        }
#pragma unroll
        for (int j = 0; j < 4; ++j) {
            int r = (wn * 32 + j * 8 + (lane >> 2)) * RSTR + kp;
            bh[j][0] = sBh[r];
            bh[j][1] = sBh[r + 4];
        }
#pragma unroll
        for (int i = 0; i < 4; ++i)
#pragma unroll
            for (int j = 0; j < 4; ++j)
                mma_bf16(acc[i][j][0], acc[i][j][1], acc[i][j][2], acc[i][j][3],
                         ah[i][0], ah[i][1], ah[i][2], ah[i][3], bh[j][0], bh[j][1]);
#pragma unroll
        for (int j = 0; j < 4; ++j) {
            int r = (wn * 32 + j * 8 + (lane >> 2)) * RSTR + kp;
            bl[j][0] = sBl[r];
            bl[j][1] = sBl[r + 4];
        }
#pragma unroll
        for (int i = 0; i < 4; ++i)
#pragma unroll
            for (int j = 0; j < 4; ++j)
                mma_bf16(acc[i][j][0], acc[i][j][1], acc[i][j][2], acc[i][j][3],
                         ah[i][0], ah[i][1], ah[i][2], ah[i][3], bl[j][0], bl[j][1]);
#pragma unroll
        for (int i = 0; i < 4; ++i) {
            int r = (wm * 64 + i * 16 + (lane >> 2)) * RSTR + kp;
            al[i][0] = sAl[r];
            al[i][1] = sAl[r + 8 * RSTR];
            al[i][2] = sAl[r + 4];
            al[i][3] = sAl[r + 8 * RSTR + 4];
        }
#pragma unroll
        for (int i = 0; i < 4; ++i)
#pragma unroll
            for (int j = 0; j < 4; ++j)
                mma_bf16(acc[i][j][0], acc[i][j][1], acc[i][j][2], acc[i][j][3],
                         al[i][0], al[i][1], al[i][2], al[i][3], bh[j][0], bh[j][1]);
    }
}

// MODE 0: relu, split -> Ch/Cl bf16.  MODE 1: fp32 -> Cf, and fp16 relu -> g_hf.
template<int MODE>
__global__ void __launch_bounds__(256, 2)
k_gemm(const __nv_bfloat16* __restrict__ Ah, const __nv_bfloat16* __restrict__ Al,
       const __nv_bfloat16* __restrict__ Bh, const __nv_bfloat16* __restrict__ Bl,
       const float* __restrict__ bias,
       __nv_bfloat16* __restrict__ Ch, __nv_bfloat16* __restrict__ Cl,
       float* __restrict__ Cf, __half* __restrict__ Cf16,
       int Mrows, int Ncols, int Kdim)
{
    extern __shared__ uint32_t sm[];
    const uint32_t smb = (uint32_t)__cvta_generic_to_shared(sm);

    const int tid  = threadIdx.x;
    const int wid  = tid >> 5;
    const int lane = tid & 31;
    const int wm   = wid >> 2;
    const int wn   = wid & 3;
    const int m0   = blockIdx.y * 128;
    const int n0   = blockIdx.x * 128;

    float acc[4][4][4];
#pragma unroll
    for (int i = 0; i < 4; ++i)
#pragma unroll
        for (int j = 0; j < 4; ++j)
#pragma unroll
            for (int r = 0; r < 4; ++r) acc[i][j][r] = 0.f;

    const int nc = Kdim >> 5;
    stage_load(smb, 0, Ah, Al, Bh, Bl, m0, n0, 0, Mrows, Kdim, tid);
    cpa_commit();

    for (int c = 0; c < nc; ++c) {
        const int s = c & 1;
        if (c + 1 < nc) {
            stage_load(smb, s ^ 1, Ah, Al, Bh, Bl, m0, n0, (c + 1) << 5, Mrows, Kdim, tid);
            cpa_commit();
            cpa_wait<1>();
        } else {
            cpa_wait<0>();
        }
        __syncthreads();
        const uint32_t* base = sm + s * (STG_B / 4);
        compute_stage(base, base + ARR_B / 4, base + 2 * (ARR_B / 4), base + 3 * (ARR_B / 4),
                      wm, wn, lane, acc);
        __syncthreads();
    }

    // ---- epilogue ----
#pragma unroll
    for (int i = 0; i < 4; ++i) {
#pragma unroll
        for (int j = 0; j < 4; ++j) {
            int cn = n0 + wn * 32 + j * 8 + 2 * (lane & 3);
            float2 bb = *(const float2*)(bias + cn);
            int rm = m0 + wm * 64 + i * 16 + (lane >> 2);
#pragma unroll
            for (int h = 0; h < 2; ++h) {
                int r = rm + h * 8;
                if (r < Mrows) {
                    float vx = acc[i][j][2 * h + 0] + bb.x;
                    float vy = acc[i][j][2 * h + 1] + bb.y;
                    size_t off = (size_t)r * Ncols + cn;
                    if (MODE == 0) {
                        vx = fmaxf(vx, 0.f);
                        vy = fmaxf(vy, 0.f);
                        __nv_bfloat16 hx = __float2bfloat16_rn(vx);
                        __nv_bfloat16 hy = __float2bfloat16_rn(vy);
                        __nv_bfloat16 lx = __float2bfloat16_rn(vx - __bfloat162float(hx));
                        __nv_bfloat16 ly = __float2bfloat16_rn(vy - __bfloat162float(hy));
                        *(uint32_t*)(Ch + off) =
                            ((uint32_t)__bfloat16_as_ushort(hy) << 16) | __bfloat16_as_ushort(hx);
                        *(uint32_t*)(Cl + off) =
                            ((uint32_t)__bfloat16_as_ushort(ly) << 16) | __bfloat16_as_ushort(lx);
                    } else {
                        *(float2*)(Cf + off) = make_float2(vx, vy);
                        __half2 hv = __floats2half2_rn(fmaxf(vx, 0.f), fmaxf(vy, 0.f));
                        *(__half2*)(Cf16 + off) = hv;
                    }
                }
            }
        }
    }
}

// ---------------- fused propagation ----------------
// out[e] = g0*h[e] + sum_k gamma[k]*P_k[e]*relu_h_fp16[idx_k[e]]
__global__ void __launch_bounds__(256)
k_final(const float* __restrict__ gamma, float* __restrict__ out)
{
    int t = blockIdx.x * blockDim.x + threadIdx.x;
    if (t >= EE * (COUT / 4)) return;
    int e = t >> 6;
    int c = (t & 63) << 2;

    float4 hv = *(const float4*)(g_h + (size_t)e * COUT + c);
    float g0 = __ldg(gamma);
    float4 acc;
    acc.x = g0 * hv.x; acc.y = g0 * hv.y;
    acc.z = g0 * hv.z; acc.w = g0 * hv.w;

#pragma unroll
    for (int k = 0; k < KHOPS; ++k) {
        int   idx = g_idx[(size_t)k * EE + e];
        float w   = __ldg(gamma + k + 1) * g_P[(size_t)k * EE + e];
        uint2 raw = *(const uint2*)(g_hf + (size_t)idx * COUT + c);
        __half2 p0 = *(__half2*)&raw.x;
        __half2 p1 = *(__half2*)&raw.y;
        float2 f0 = __half22float2(p0);
        float2 f1 = __half22float2(p1);
        acc.x += w * f0.x;
        acc.y += w * f0.y;
        acc.z += w * f1.x;
        acc.w += w * f1.y;
    }
    *(float4*)(out + (size_t)e * COUT + c) = acc;
}

// ---------------- launch ----------------
extern "C" void kernel_launch(void* const* d_in, const int* in_sizes, int n_in,
                              void* d_out, int out_size)
{
    const float* x     = nullptr;
    const int*   ei    = nullptr;
    const float* W1    = nullptr;
    const float* b1    = nullptr;
    const float* W2    = nullptr;
    const float* b2    = nullptr;
    const float* gamma = nullptr;
    for (int i = 0; i < n_in; ++i) {
        switch (in_sizes[i]) {
            case 102400000: x     = (const float*)d_in[i]; break;
            case 400000:    ei    = (const int*)d_in[i];   break;
            case 262144:    W1    = (const float*)d_in[i]; break;
            case 512:       b1    = (const float*)d_in[i]; break;
            case 131072:    W2    = (const float*)d_in[i]; break;
            case 256:       b2    = (const float*)d_in[i]; break;
            case 11:        gamma = (const float*)d_in[i]; break;
        }
    }
    float* out = (float*)d_out;

    k_detect<<<1, 256>>>(ei);
    k_zero_deg<<<(NN + 255) / 256, 256>>>();
    k_count<<<(EE + 255) / 256, 256>>>(ei);
    k_coef<<<(EE + 255) / 256, 256>>>(ei);

    const int eb = (EE + 255) / 256;
    k_chain<<<eb, 256>>>();

    __nv_bfloat16 *w1h, *w1l, *w2h, *w2l, *xh, *xl, *t1h, *t1l;
    float *hbuf;
    __half *hfbuf;
    cudaGetSymbolAddress((void**)&w1h, g_W1h);
    cudaGetSymbolAddress((void**)&w1l, g_W1l);
    cudaGetSymbolAddress((void**)&w2h, g_W2h);
    cudaGetSymbolAddress((void**)&w2l, g_W2l);
    cudaGetSymbolAddress((void**)&xh,  g_xh);
    cudaGetSymbolAddress((void**)&xl,  g_xl);
    cudaGetSymbolAddress((void**)&t1h, g_t1h);
    cudaGetSymbolAddress((void**)&t1l, g_t1l);
    cudaGetSymbolAddress((void**)&hbuf, g_h);
    cudaGetSymbolAddress((void**)&hfbuf, g_hf);

    k_prep_w<<<(CIN * CHID + 255) / 256, 256>>>(W1, w1h, w1l, CIN, CHID);
    k_prep_w<<<(CHID * COUT + 255) / 256, 256>>>(W2, w2h, w2l, CHID, COUT);

    cudaFuncSetAttribute(k_gemm<0>, cudaFuncAttributeMaxDynamicSharedMemorySize, 2 * STG_B);
    cudaFuncSetAttribute(k_gemm<1>, cudaFuncAttributeMaxDynamicSharedMemorySize, 2 * STG_B);

    const int mt = (CHUNK + 127) / 128;
    dim3 g1(CHID / 128, mt);
    dim3 g2(COUT / 128, mt);
    const int splitN4 = CHUNK * CIN / 4;
    for (int row0 = 0; row0 < NN; row0 += CHUNK) {
        k_split<<<(splitN4 + 255) / 256, 256>>>(x + (size_t)row0 * CIN, xh, xl, splitN4);
        k_gemm<0><<<g1, 256, 2 * STG_B>>>(xh, xl, w1h, w1l, b1,
                                          t1h, t1l, nullptr, nullptr, CHUNK, CHID, CIN);
        k_gemm<1><<<g2, 256, 2 * STG_B>>>(t1h, t1l, w2h, w2l, b2,
                                          nullptr, nullptr,
                                          hbuf + (size_t)row0 * COUT,
                                          hfbuf + (size_t)row0 * COUT,
                                          CHUNK, COUT, CHID);
    }

    const int total = EE * (COUT / 4);
    k_final<<<(total + 255) / 256, 256>>>(gamma, out);
}

// round 15
// speedup vs baseline: 1.0778x; 1.0778x over previous
#include <cuda_runtime.h>
#include <cuda_bf16.h>
#include <cuda_fp16.h>
#include <cstdint>
#include <cstddef>

#define NN    200000
#define EE    200000
#define CIN   512
#define CHID  512
#define COUT  256
#define KHOPS 10
#define CHUNK 50000     // 4 chunks of rows through the MLP

// ---------------- device scratch (static; no allocation) ----------------
__device__ int           g_is64;
__device__ unsigned int  g_degi[NN];
__device__ __align__(16) float g_coef[EE];
__device__ int           g_col[EE];
__device__ int           g_idx[(size_t)KHOPS * EE];     // col^k chains
__device__ __align__(16) float g_P[(size_t)KHOPS * EE]; // cumulative coef products
__device__ __align__(16) float g_h[(size_t)NN * COUT];  // MLP output (fp32)
__device__ __align__(16) __half g_hf[(size_t)NN * COUT]; // relu(h) in fp16 (gather path)
// per-chunk split activations
__device__ __align__(16) __nv_bfloat16 g_xh[(size_t)CHUNK * CIN];
__device__ __align__(16) __nv_bfloat16 g_xl[(size_t)CHUNK * CIN];
__device__ __align__(16) __nv_bfloat16 g_t1h[(size_t)CHUNK * CHID];
__device__ __align__(16) __nv_bfloat16 g_t1l[(size_t)CHUNK * CHID];
// transposed + bf16-split weights: Wt[n][k] = W[k][n]
__device__ __align__(16) __nv_bfloat16 g_W1h[(size_t)CHID * CIN];
__device__ __align__(16) __nv_bfloat16 g_W1l[(size_t)CHID * CIN];
__device__ __align__(16) __nv_bfloat16 g_W2h[(size_t)COUT * CHID];
__device__ __align__(16) __nv_bfloat16 g_W2l[(size_t)COUT * CHID];

// ---------------- edge_index dtype detection ----------------
__global__ void k_detect(const int* __restrict__ buf) {
    __shared__ int nz;
    if (threadIdx.x == 0) nz = 0;
    __syncthreads();
    int local = 0;
    for (int i = threadIdx.x; i < 1024; i += blockDim.x)
        if (buf[2 * i + 1] != 0) local = 1;
    if (local) atomicOr(&nz, 1);
    __syncthreads();
    if (threadIdx.x == 0) g_is64 = (nz == 0) ? 1 : 0;
}
__device__ __forceinline__ int edge_row(const int* buf, int e) {
    int v = g_is64 ? buf[2 * e] : buf[e];
    unsigned u = (unsigned)v;
    return (u < NN) ? (int)u : 0;
}
__device__ __forceinline__ int edge_col(const int* buf, int e) {
    int v = g_is64 ? buf[2 * (EE + e)] : buf[EE + e];
    unsigned u = (unsigned)v;
    return (u < NN) ? (int)u : 0;
}

// ---------------- graph prep ----------------
__global__ void k_zero_deg() {
    int i = blockIdx.x * blockDim.x + threadIdx.x;
    if (i < NN) g_degi[i] = 0u;
}
__global__ void k_count(const int* __restrict__ ei) {
    int e = blockIdx.x * blockDim.x + threadIdx.x;
    if (e < EE) atomicAdd(&g_degi[edge_row(ei, e)], 1u);
}
__global__ void k_coef(const int* __restrict__ ei) {
    int e = blockIdx.x * blockDim.x + threadIdx.x;
    if (e >= EE) return;
    int r = edge_row(ei, e);
    int c = edge_col(ei, e);
    float dr = (float)g_degi[r], dc = (float)g_degi[c];
    float ir = dr > 0.f ? rsqrtf(dr) : 0.f;
    float ic = dc > 0.f ? rsqrtf(dc) : 0.f;
    g_coef[e] = ir * ic;
    g_col[e]  = c;
}

// ---------------- hop-chain precompute (single kernel, serial walk) ----------------
__global__ void k_chain() {
    int e = blockIdx.x * blockDim.x + threadIdx.x;
    if (e >= EE) return;
    int   cur = g_col[e];
    float p   = g_coef[e];
    g_idx[e] = cur;
    g_P[e]   = p;
#pragma unroll
    for (int k = 1; k < KHOPS; ++k) {
        p  *= g_coef[cur];
        cur = g_col[cur];
        g_idx[(size_t)k * EE + e] = cur;
        g_P[(size_t)k * EE + e]   = p;
    }
}

// ---------------- weight transpose + bf16 split ----------------
__global__ void k_prep_w(const float* __restrict__ W, __nv_bfloat16* __restrict__ Th,
                         __nv_bfloat16* __restrict__ Tl, int Kdim, int Ncols) {
    int i = blockIdx.x * blockDim.x + threadIdx.x;
    if (i >= Kdim * Ncols) return;
    int n = i / Kdim, k = i % Kdim;
    float v = W[(size_t)k * Ncols + n];
    __nv_bfloat16 h = __float2bfloat16_rn(v);
    Th[i] = h;
    Tl[i] = __float2bfloat16_rn(v - __bfloat162float(h));
}

// ---------------- fp32 -> bf16 hi/lo split ----------------
__global__ void k_split(const float* __restrict__ src,
                        __nv_bfloat16* __restrict__ Th,
                        __nv_bfloat16* __restrict__ Tl, int n4) {
    int i = blockIdx.x * blockDim.x + threadIdx.x;
    if (i >= n4) return;
    float4 v = ((const float4*)src)[i];
    float f[4] = {v.x, v.y, v.z, v.w};
    uint32_t h[2], l[2];
#pragma unroll
    for (int p = 0; p < 2; ++p) {
        __nv_bfloat16 h0 = __float2bfloat16_rn(f[2 * p]);
        __nv_bfloat16 h1 = __float2bfloat16_rn(f[2 * p + 1]);
        __nv_bfloat16 l0 = __float2bfloat16_rn(f[2 * p]     - __bfloat162float(h0));
        __nv_bfloat16 l1 = __float2bfloat16_rn(f[2 * p + 1] - __bfloat162float(h1));
        h[p] = ((uint32_t)__bfloat16_as_ushort(h1) << 16) | __bfloat16_as_ushort(h0);
        l[p] = ((uint32_t)__bfloat16_as_ushort(l1) << 16) | __bfloat16_as_ushort(l0);
    }
    ((uint2*)Th)[i] = make_uint2(h[0], h[1]);
    ((uint2*)Tl)[i] = make_uint2(l[0], l[1]);
}

// ---------------- warp-MMA bf16-split GEMM, cp.async double-buffered ----------------
#define RSTR     20
#define ARR_B    10240
#define STG_B    40960

__device__ __forceinline__ void cpa16(uint32_t dst, const void* src) {
    asm volatile("cp.async.cg.shared.global [%0], [%1], 16;" :: "r"(dst), "l"(src));
}
__device__ __forceinline__ void cpa_commit() {
    asm volatile("cp.async.commit_group;");
}
template<int N>
__device__ __forceinline__ void cpa_wait() {
    asm volatile("cp.async.wait_group %0;" :: "n"(N));
}
__device__ __forceinline__ void mma_bf16(float& d0, float& d1, float& d2, float& d3,
                                         uint32_t a0, uint32_t a1, uint32_t a2, uint32_t a3,
                                         uint32_t b0, uint32_t b1) {
    asm volatile(
        "mma.sync.aligned.m16n8k16.row.col.f32.bf16.bf16.f32 "
        "{%0,%1,%2,%3}, {%4,%5,%6,%7}, {%8,%9}, {%0,%1,%2,%3};"
        : "+f"(d0), "+f"(d1), "+f"(d2), "+f"(d3)
        : "r"(a0), "r"(a1), "r"(a2), "r"(a3), "r"(b0), "r"(b1));
}

__device__ __forceinline__ void stage_load(uint32_t smb, int s,
        const __nv_bfloat16* Ah, const __nv_bfloat16* Al,
        const __nv_bfloat16* Bh, const __nv_bfloat16* Bl,
        int m0, int n0, int k0, int Mrows, int Kdim, int tid)
{
    uint32_t base = smb + s * STG_B;
#pragma unroll
    for (int uu = 0; uu < 2; ++uu) {
        int u   = tid + uu * 256;
        int row = u >> 2, seg = u & 3;
        int m = m0 + row;
        if (m >= Mrows) m = Mrows - 1;
        size_t ao = (size_t)m * Kdim + k0 + seg * 8;
        size_t bo = (size_t)(n0 + row) * Kdim + k0 + seg * 8;
        uint32_t d = base + row * 80 + seg * 16;
        cpa16(d,             Ah + ao);
        cpa16(d + ARR_B,     Al + ao);
        cpa16(d + 2 * ARR_B, Bh + bo);
        cpa16(d + 3 * ARR_B, Bl + bo);
    }
}

__device__ __forceinline__ void compute_stage(const uint32_t* sAh, const uint32_t* sAl,
        const uint32_t* sBh, const uint32_t* sBl,
        int wm, int wn, int lane, float acc[4][4][4])
{
#pragma unroll
    for (int ks = 0; ks < 2; ++ks) {
        const int kp = ks * 8 + (lane & 3);
        uint32_t ah[4][4], bh[4][2], bl[4][2], al[4][4];
#pragma unroll
        for (int i = 0; i < 4; ++i) {
            int r = (wm * 64 + i * 16 + (lane >> 2)) * RSTR + kp;
            ah[i][0] = sAh[r];
            ah[i][1] = sAh[r + 8 * RSTR];
            ah[i][2] = sAh[r + 4];
            ah[i][3] = sAh[r + 8 * RSTR + 4];
        }
#pragma unroll
        for (int j = 0; j < 4; ++j) {
            int r = (wn * 32 + j * 8 + (lane >> 2)) * RSTR + kp;
            bh[j][0] = sBh[r];
            bh[j][1] = sBh[r + 4];
        }
#pragma unroll
        for (int i = 0; i < 4; ++i)
#pragma unroll
            for (int j = 0; j < 4; ++j)
                mma_bf16(acc[i][j][0], acc[i][j][1], acc[i][j][2], acc[i][j][3],
                         ah[i][0], ah[i][1], ah[i][2], ah[i][3], bh[j][0], bh[j][1]);
#pragma unroll
        for (int j = 0; j < 4; ++j) {
            int r = (wn * 32 + j * 8 + (lane >> 2)) * RSTR + kp;
            bl[j][0] = sBl[r];
            bl[j][1] = sBl[r + 4];
        }
#pragma unroll
        for (int i = 0; i < 4; ++i)
#pragma unroll
            for (int j = 0; j < 4; ++j)
                mma_bf16(acc[i][j][0], acc[i][j][1], acc[i][j][2], acc[i][j][3],
                         ah[i][0], ah[i][1], ah[i][2], ah[i][3], bl[j][0], bl[j][1]);
#pragma unroll
        for (int i = 0; i < 4; ++i) {
            int r = (wm * 64 + i * 16 + (lane >> 2)) * RSTR + kp;
            al[i][0] = sAl[r];
            al[i][1] = sAl[r + 8 * RSTR];
            al[i][2] = sAl[r + 4];
            al[i][3] = sAl[r + 8 * RSTR + 4];
        }
#pragma unroll
        for (int i = 0; i < 4; ++i)
#pragma unroll
            for (int j = 0; j < 4; ++j)
                mma_bf16(acc[i][j][0], acc[i][j][1], acc[i][j][2], acc[i][j][3],
                         al[i][0], al[i][1], al[i][2], al[i][3], bh[j][0], bh[j][1]);
    }
}

// MODE 0: relu, split -> Ch/Cl bf16.  MODE 1: fp32 -> Cf, and fp16 relu -> Cf16.
template<int MODE>
__global__ void __launch_bounds__(256, 2)
k_gemm(const __nv_bfloat16* __restrict__ Ah, const __nv_bfloat16* __restrict__ Al,
       const __nv_bfloat16* __restrict__ Bh, const __nv_bfloat16* __restrict__ Bl,
       const float* __restrict__ bias,
       __nv_bfloat16* __restrict__ Ch, __nv_bfloat16* __restrict__ Cl,
       float* __restrict__ Cf, __half* __restrict__ Cf16,
       int Mrows, int Ncols, int Kdim)
{
    extern __shared__ uint32_t sm[];
    const uint32_t smb = (uint32_t)__cvta_generic_to_shared(sm);

    const int tid  = threadIdx.x;
    const int wid  = tid >> 5;
    const int lane = tid & 31;
    const int wm   = wid >> 2;
    const int wn   = wid & 3;
    const int m0   = blockIdx.y * 128;
    const int n0   = blockIdx.x * 128;

    float acc[4][4][4];
#pragma unroll
    for (int i = 0; i < 4; ++i)
#pragma unroll
        for (int j = 0; j < 4; ++j)
#pragma unroll
            for (int r = 0; r < 4; ++r) acc[i][j][r] = 0.f;

    const int nc = Kdim >> 5;
    stage_load(smb, 0, Ah, Al, Bh, Bl, m0, n0, 0, Mrows, Kdim, tid);
    cpa_commit();

    for (int c = 0; c < nc; ++c) {
        const int s = c & 1;
        if (c + 1 < nc) {
            stage_load(smb, s ^ 1, Ah, Al, Bh, Bl, m0, n0, (c + 1) << 5, Mrows, Kdim, tid);
            cpa_commit();
            cpa_wait<1>();
        } else {
            cpa_wait<0>();
        }
        __syncthreads();
        const uint32_t* base = sm + s * (STG_B / 4);
        compute_stage(base, base + ARR_B / 4, base + 2 * (ARR_B / 4), base + 3 * (ARR_B / 4),
                      wm, wn, lane, acc);
        __syncthreads();
    }

    // ---- epilogue ----
#pragma unroll
    for (int i = 0; i < 4; ++i) {
#pragma unroll
        for (int j = 0; j < 4; ++j) {
            int cn = n0 + wn * 32 + j * 8 + 2 * (lane & 3);
            float2 bb = *(const float2*)(bias + cn);
            int rm = m0 + wm * 64 + i * 16 + (lane >> 2);
#pragma unroll
            for (int h = 0; h < 2; ++h) {
                int r = rm + h * 8;
                if (r < Mrows) {
                    float vx = acc[i][j][2 * h + 0] + bb.x;
                    float vy = acc[i][j][2 * h + 1] + bb.y;
                    size_t off = (size_t)r * Ncols + cn;
                    if (MODE == 0) {
                        vx = fmaxf(vx, 0.f);
                        vy = fmaxf(vy, 0.f);
                        __nv_bfloat16 hx = __float2bfloat16_rn(vx);
                        __nv_bfloat16 hy = __float2bfloat16_rn(vy);
                        __nv_bfloat16 lx = __float2bfloat16_rn(vx - __bfloat162float(hx));
                        __nv_bfloat16 ly = __float2bfloat16_rn(vy - __bfloat162float(hy));
                        *(uint32_t*)(Ch + off) =
                            ((uint32_t)__bfloat16_as_ushort(hy) << 16) | __bfloat16_as_ushort(hx);
                        *(uint32_t*)(Cl + off) =
                            ((uint32_t)__bfloat16_as_ushort(ly) << 16) | __bfloat16_as_ushort(lx);
                    } else {
                        *(float2*)(Cf + off) = make_float2(vx, vy);
                        __half2 hv = __floats2half2_rn(fmaxf(vx, 0.f), fmaxf(vy, 0.f));
                        *(__half2*)(Cf16 + off) = hv;
                    }
                }
            }
        }
    }
}

// ---------------- fused propagation ----------------
// out[e] = g0*h[e] + sum_k gamma[k]*P_k[e]*relu_h_fp16[idx_k[e]]
__global__ void __launch_bounds__(256)
k_final(const float* __restrict__ gamma, float* __restrict__ out)
{
    int t = blockIdx.x * blockDim.x + threadIdx.x;
    if (t >= EE * (COUT / 4)) return;
    int e = t >> 6;
    int c = (t & 63) << 2;

    float4 hv = *(const float4*)(g_h + (size_t)e * COUT + c);
    float g0 = __ldg(gamma);
    float4 acc;
    acc.x = g0 * hv.x; acc.y = g0 * hv.y;
    acc.z = g0 * hv.z; acc.w = g0 * hv.w;

#pragma unroll
    for (int k = 0; k < KHOPS; ++k) {
        int   idx = g_idx[(size_t)k * EE + e];
        float w   = __ldg(gamma + k + 1) * g_P[(size_t)k * EE + e];
        uint2 raw = *(const uint2*)(g_hf + (size_t)idx * COUT + c);
        __half2 p0 = *(__half2*)&raw.x;
        __half2 p1 = *(__half2*)&raw.y;
        float2 f0 = __half22float2(p0);
        float2 f1 = __half22float2(p1);
        acc.x += w * f0.x;
        acc.y += w * f0.y;
        acc.z += w * f1.x;
        acc.w += w * f1.y;
    }
    *(float4*)(out + (size_t)e * COUT + c) = acc;
}

// ---------------- launch ----------------
extern "C" void kernel_launch(void* const* d_in, const int* in_sizes, int n_in,
                              void* d_out, int out_size)
{
    const float* x     = nullptr;
    const int*   ei    = nullptr;
    const float* W1    = nullptr;
    const float* b1    = nullptr;
    const float* W2    = nullptr;
    const float* b2    = nullptr;
    const float* gamma = nullptr;
    for (int i = 0; i < n_in; ++i) {
        switch (in_sizes[i]) {
            case 102400000: x     = (const float*)d_in[i]; break;
            case 400000:    ei    = (const int*)d_in[i];   break;
            case 262144:    W1    = (const float*)d_in[i]; break;
            case 512:       b1    = (const float*)d_in[i]; break;
            case 131072:    W2    = (const float*)d_in[i]; break;
            case 256:       b2    = (const float*)d_in[i]; break;
            case 11:        gamma = (const float*)d_in[i]; break;
        }
    }
    float* out = (float*)d_out;

    k_detect<<<1, 256>>>(ei);
    k_zero_deg<<<(NN + 255) / 256, 256>>>();
    k_count<<<(EE + 255) / 256, 256>>>(ei);
    k_coef<<<(EE + 255) / 256, 256>>>(ei);

    const int eb = (EE + 255) / 256;
    k_chain<<<eb, 256>>>();

    __nv_bfloat16 *w1h, *w1l, *w2h, *w2l, *xh, *xl, *t1h, *t1l;
    float *hbuf;
    __half *hfbuf;
    cudaGetSymbolAddress((void**)&w1h, g_W1h);
    cudaGetSymbolAddress((void**)&w1l, g_W1l);
    cudaGetSymbolAddress((void**)&w2h, g_W2h);
    cudaGetSymbolAddress((void**)&w2l, g_W2l);
    cudaGetSymbolAddress((void**)&xh,  g_xh);
    cudaGetSymbolAddress((void**)&xl,  g_xl);
    cudaGetSymbolAddress((void**)&t1h, g_t1h);
    cudaGetSymbolAddress((void**)&t1l, g_t1l);
    cudaGetSymbolAddress((void**)&hbuf, g_h);
    cudaGetSymbolAddress((void**)&hfbuf, g_hf);

    k_prep_w<<<(CIN * CHID + 255) / 256, 256>>>(W1, w1h, w1l, CIN, CHID);
    k_prep_w<<<(CHID * COUT + 255) / 256, 256>>>(W2, w2h, w2l, CHID, COUT);

    cudaFuncSetAttribute(k_gemm<0>, cudaFuncAttributeMaxDynamicSharedMemorySize, 2 * STG_B);
    cudaFuncSetAttribute(k_gemm<1>, cudaFuncAttributeMaxDynamicSharedMemorySize, 2 * STG_B);

    const int mt = (CHUNK + 127) / 128;
    dim3 g1(CHID / 128, mt);
    dim3 g2(COUT / 128, mt);
    const int splitN4 = CHUNK * CIN / 4;
    for (int row0 = 0; row0 < NN; row0 += CHUNK) {
        k_split<<<(splitN4 + 255) / 256, 256>>>(x + (size_t)row0 * CIN, xh, xl, splitN4);
        k_gemm<0><<<g1, 256, 2 * STG_B>>>(xh, xl, w1h, w1l, b1,
                                          t1h, t1l, nullptr, nullptr, CHUNK, CHID, CIN);
        k_gemm<1><<<g2, 256, 2 * STG_B>>>(t1h, t1l, w2h, w2l, b2,
                                          nullptr, nullptr,
                                          hbuf + (size_t)row0 * COUT,
                                          hfbuf + (size_t)row0 * COUT,
                                          CHUNK, COUT, CHID);
    }

    const int total = EE * (COUT / 4);
    k_final<<<(total + 255) / 256, 256>>>(gamma, out);
}

// round 16
// speedup vs baseline: 1.0996x; 1.0202x over previous
#include <cuda_runtime.h>
#include <cuda_bf16.h>
#include <cuda_fp16.h>
#include <cstdint>
#include <cstddef>

#define NN    200000
#define EE    200000
#define CIN   512
#define CHID  512
#define COUT  256
#define KHOPS 10
#define CHUNK 50000     // 4 chunks of rows through the MLP

// ---------------- device scratch (static; no allocation) ----------------
__device__ int           g_is64;
__device__ unsigned int  g_degi[NN];
__device__ __align__(16) float g_coef[EE];
__device__ int           g_col[EE];
__device__ int           g_idx[(size_t)KHOPS * EE];     // col^k chains
__device__ __align__(16) float g_P[(size_t)KHOPS * EE]; // cumulative coef products
__device__ __align__(16) float g_h[(size_t)NN * COUT];  // MLP output (fp32)
__device__ __align__(16) __half g_hf[(size_t)NN * COUT]; // relu(h) in fp16 (gather path)
// per-chunk hidden activations (bf16 hi/lo, produced by GEMM1 epilogue)
__device__ __align__(16) __nv_bfloat16 g_t1h[(size_t)CHUNK * CHID];
__device__ __align__(16) __nv_bfloat16 g_t1l[(size_t)CHUNK * CHID];
// transposed + bf16-split weights: Wt[n][k] = W[k][n]
__device__ __align__(16) __nv_bfloat16 g_W1h[(size_t)CHID * CIN];
__device__ __align__(16) __nv_bfloat16 g_W1l[(size_t)CHID * CIN];
__device__ __align__(16) __nv_bfloat16 g_W2h[(size_t)COUT * CHID];
__device__ __align__(16) __nv_bfloat16 g_W2l[(size_t)COUT * CHID];

// ---------------- edge_index dtype detection ----------------
__global__ void k_detect(const int* __restrict__ buf) {
    __shared__ int nz;
    if (threadIdx.x == 0) nz = 0;
    __syncthreads();
    int local = 0;
    for (int i = threadIdx.x; i < 1024; i += blockDim.x)
        if (buf[2 * i + 1] != 0) local = 1;
    if (local) atomicOr(&nz, 1);
    __syncthreads();
    if (threadIdx.x == 0) g_is64 = (nz == 0) ? 1 : 0;
}
__device__ __forceinline__ int edge_row(const int* buf, int e) {
    int v = g_is64 ? buf[2 * e] : buf[e];
    unsigned u = (unsigned)v;
    return (u < NN) ? (int)u : 0;
}
__device__ __forceinline__ int edge_col(const int* buf, int e) {
    int v = g_is64 ? buf[2 * (EE + e)] : buf[EE + e];
    unsigned u = (unsigned)v;
    return (u < NN) ? (int)u : 0;
}

// ---------------- graph prep ----------------
__global__ void k_zero_deg() {
    int i = blockIdx.x * blockDim.x + threadIdx.x;
    if (i < NN) g_degi[i] = 0u;
}
__global__ void k_count(const int* __restrict__ ei) {
    int e = blockIdx.x * blockDim.x + threadIdx.x;
    if (e < EE) atomicAdd(&g_degi[edge_row(ei, e)], 1u);
}
__global__ void k_coef(const int* __restrict__ ei) {
    int e = blockIdx.x * blockDim.x + threadIdx.x;
    if (e >= EE) return;
    int r = edge_row(ei, e);
    int c = edge_col(ei, e);
    float dr = (float)g_degi[r], dc = (float)g_degi[c];
    float ir = dr > 0.f ? rsqrtf(dr) : 0.f;
    float ic = dc > 0.f ? rsqrtf(dc) : 0.f;
    g_coef[e] = ir * ic;
    g_col[e]  = c;
}

// ---------------- hop-chain precompute (single kernel, serial walk) ----------------
__global__ void k_chain() {
    int e = blockIdx.x * blockDim.x + threadIdx.x;
    if (e >= EE) return;
    int   cur = g_col[e];
    float p   = g_coef[e];
    g_idx[e] = cur;
    g_P[e]   = p;
#pragma unroll
    for (int k = 1; k < KHOPS; ++k) {
        p  *= g_coef[cur];
        cur = g_col[cur];
        g_idx[(size_t)k * EE + e] = cur;
        g_P[(size_t)k * EE + e]   = p;
    }
}

// ---------------- weight transpose + bf16 split ----------------
__global__ void k_prep_w(const float* __restrict__ W, __nv_bfloat16* __restrict__ Th,
                         __nv_bfloat16* __restrict__ Tl, int Kdim, int Ncols) {
    int i = blockIdx.x * blockDim.x + threadIdx.x;
    if (i >= Kdim * Ncols) return;
    int n = i / Kdim, k = i % Kdim;
    float v = W[(size_t)k * Ncols + n];
    __nv_bfloat16 h = __float2bfloat16_rn(v);
    Th[i] = h;
    Tl[i] = __float2bfloat16_rn(v - __bfloat162float(h));
}

// ---------------- shared GEMM helpers ----------------
#define RSTR     20
#define ARR_B    10240
#define STG_B    40960
// GEMM1 (fp32-A) layout
#define A1_AF_ROWB  144                  // fp32 A row stride bytes (36 floats)
#define A1_BH_OFF   18432                // 128*144
#define A1_BL_OFF   28672
#define A1_STG      38912                // per-stage bytes
#define A1_AH_OFF   77824                // single-buffered bf16 hi
#define A1_AL_OFF   88064
#define SMEM1       98304

__device__ __forceinline__ void cpa16(uint32_t dst, const void* src) {
    asm volatile("cp.async.cg.shared.global [%0], [%1], 16;" :: "r"(dst), "l"(src));
}
__device__ __forceinline__ void cpa_commit() {
    asm volatile("cp.async.commit_group;");
}
template<int N>
__device__ __forceinline__ void cpa_wait() {
    asm volatile("cp.async.wait_group %0;" :: "n"(N));
}
__device__ __forceinline__ void mma_bf16(float& d0, float& d1, float& d2, float& d3,
                                         uint32_t a0, uint32_t a1, uint32_t a2, uint32_t a3,
                                         uint32_t b0, uint32_t b1) {
    asm volatile(
        "mma.sync.aligned.m16n8k16.row.col.f32.bf16.bf16.f32 "
        "{%0,%1,%2,%3}, {%4,%5,%6,%7}, {%8,%9}, {%0,%1,%2,%3};"
        : "+f"(d0), "+f"(d1), "+f"(d2), "+f"(d3)
        : "r"(a0), "r"(a1), "r"(a2), "r"(a3), "r"(b0), "r"(b1));
}
__device__ __forceinline__ uint32_t pack_hi(float a, float b, uint32_t& lo) {
    __nv_bfloat16 h0 = __float2bfloat16_rn(a);
    __nv_bfloat16 h1 = __float2bfloat16_rn(b);
    __nv_bfloat16 l0 = __float2bfloat16_rn(a - __bfloat162float(h0));
    __nv_bfloat16 l1 = __float2bfloat16_rn(b - __bfloat162float(h1));
    lo = ((uint32_t)__bfloat16_as_ushort(l1) << 16) | __bfloat16_as_ushort(l0);
    return ((uint32_t)__bfloat16_as_ushort(h1) << 16) | __bfloat16_as_ushort(h0);
}

__device__ __forceinline__ void compute_stage(const uint32_t* sAh, const uint32_t* sAl,
        const uint32_t* sBh, const uint32_t* sBl,
        int wm, int wn, int lane, float acc[4][4][4])
{
#pragma unroll
    for (int ks = 0; ks < 2; ++ks) {
        const int kp = ks * 8 + (lane & 3);
        uint32_t ah[4][4], bh[4][2], bl[4][2], al[4][4];
#pragma unroll
        for (int i = 0; i < 4; ++i) {
            int r = (wm * 64 + i * 16 + (lane >> 2)) * RSTR + kp;
            ah[i][0] = sAh[r];
            ah[i][1] = sAh[r + 8 * RSTR];
            ah[i][2] = sAh[r + 4];
            ah[i][3] = sAh[r + 8 * RSTR + 4];
        }
#pragma unroll
        for (int j = 0; j < 4; ++j) {
            int r = (wn * 32 + j * 8 + (lane >> 2)) * RSTR + kp;
            bh[j][0] = sBh[r];
            bh[j][1] = sBh[r + 4];
        }
#pragma unroll
        for (int i = 0; i < 4; ++i)
#pragma unroll
            for (int j = 0; j < 4; ++j)
                mma_bf16(acc[i][j][0], acc[i][j][1], acc[i][j][2], acc[i][j][3],
                         ah[i][0], ah[i][1], ah[i][2], ah[i][3], bh[j][0], bh[j][1]);
#pragma unroll
        for (int j = 0; j < 4; ++j) {
            int r = (wn * 32 + j * 8 + (lane >> 2)) * RSTR + kp;
            bl[j][0] = sBl[r];
            bl[j][1] = sBl[r + 4];
        }
#pragma unroll
        for (int i = 0; i < 4; ++i)
#pragma unroll
            for (int j = 0; j < 4; ++j)
                mma_bf16(acc[i][j][0], acc[i][j][1], acc[i][j][2], acc[i][j][3],
                         ah[i][0], ah[i][1], ah[i][2], ah[i][3], bl[j][0], bl[j][1]);
#pragma unroll
        for (int i = 0; i < 4; ++i) {
            int r = (wm * 64 + i * 16 + (lane >> 2)) * RSTR + kp;
            al[i][0] = sAl[r];
            al[i][1] = sAl[r + 8 * RSTR];
            al[i][2] = sAl[r + 4];
            al[i][3] = sAl[r + 8 * RSTR + 4];
        }
#pragma unroll
        for (int i = 0; i < 4; ++i)
#pragma unroll
            for (int j = 0; j < 4; ++j)
                mma_bf16(acc[i][j][0], acc[i][j][1], acc[i][j][2], acc[i][j][3],
                         al[i][0], al[i][1], al[i][2], al[i][3], bh[j][0], bh[j][1]);
    }
}

// ---------------- GEMM1: fp32 A staged + in-smem split; relu+split epilogue ----------------
__global__ void __launch_bounds__(256, 2)
k_gemm1(const float* __restrict__ A,
        const __nv_bfloat16* __restrict__ Bh, const __nv_bfloat16* __restrict__ Bl,
        const float* __restrict__ bias,
        __nv_bfloat16* __restrict__ Ch, __nv_bfloat16* __restrict__ Cl,
        int Mrows, int Ncols, int Kdim)
{
    extern __shared__ char sm1[];
    const uint32_t smb = (uint32_t)__cvta_generic_to_shared(sm1);

    const int tid  = threadIdx.x;
    const int wid  = tid >> 5;
    const int lane = tid & 31;
    const int wm   = wid >> 2;
    const int wn   = wid & 3;
    const int m0   = blockIdx.y * 128;
    const int n0   = blockIdx.x * 128;

    float acc[4][4][4];
#pragma unroll
    for (int i = 0; i < 4; ++i)
#pragma unroll
        for (int j = 0; j < 4; ++j)
#pragma unroll
            for (int r = 0; r < 4; ++r) acc[i][j][r] = 0.f;

    auto stage_load = [&](int s, int k0) {
        uint32_t base = smb + s * A1_STG;
        // A fp32: 128 rows x 32 cols = 1024 16B chunks
#pragma unroll
        for (int uu = 0; uu < 4; ++uu) {
            int u = tid + uu * 256;
            int row = u >> 3, seg = u & 7;
            int m = m0 + row;
            if (m >= Mrows) m = Mrows - 1;
            cpa16(base + row * A1_AF_ROWB + seg * 16,
                  A + (size_t)m * Kdim + k0 + seg * 4);
        }
        // B bf16 pair: 128 rows x 32 cols
#pragma unroll
        for (int uu = 0; uu < 2; ++uu) {
            int u = tid + uu * 256;
            int row = u >> 2, seg = u & 3;
            size_t bo = (size_t)(n0 + row) * Kdim + k0 + seg * 8;
            uint32_t d = base + A1_BH_OFF + row * 80 + seg * 16;
            cpa16(d, Bh + bo);
            cpa16(d + ARR_B, Bl + bo);
        }
    };

    const int nc = Kdim >> 5;
    stage_load(0, 0);
    cpa_commit();

    for (int c = 0; c < nc; ++c) {
        const int s = c & 1;
        if (c + 1 < nc) {
            stage_load(s ^ 1, (c + 1) << 5);
            cpa_commit();
            cpa_wait<1>();
        } else {
            cpa_wait<0>();
        }
        __syncthreads();
        // convert fp32 A tile -> bf16 hi/lo in RSTR layout
        {
            const int row = tid >> 1, hh = tid & 1;
            const float* af = (const float*)(sm1 + s * A1_STG + row * A1_AF_ROWB) + hh * 16;
            float4 v0 = ((const float4*)af)[0];
            float4 v1 = ((const float4*)af)[1];
            float4 v2 = ((const float4*)af)[2];
            float4 v3 = ((const float4*)af)[3];
            uint32_t h[8], l[8];
            h[0] = pack_hi(v0.x, v0.y, l[0]);
            h[1] = pack_hi(v0.z, v0.w, l[1]);
            h[2] = pack_hi(v1.x, v1.y, l[2]);
            h[3] = pack_hi(v1.z, v1.w, l[3]);
            h[4] = pack_hi(v2.x, v2.y, l[4]);
            h[5] = pack_hi(v2.z, v2.w, l[5]);
            h[6] = pack_hi(v3.x, v3.y, l[6]);
            h[7] = pack_hi(v3.z, v3.w, l[7]);
            uint32_t* dh = (uint32_t*)(sm1 + A1_AH_OFF) + row * RSTR + hh * 8;
            uint32_t* dl = (uint32_t*)(sm1 + A1_AL_OFF) + row * RSTR + hh * 8;
            ((uint4*)dh)[0] = make_uint4(h[0], h[1], h[2], h[3]);
            ((uint4*)dh)[1] = make_uint4(h[4], h[5], h[6], h[7]);
            ((uint4*)dl)[0] = make_uint4(l[0], l[1], l[2], l[3]);
            ((uint4*)dl)[1] = make_uint4(l[4], l[5], l[6], l[7]);
        }
        __syncthreads();
        compute_stage((const uint32_t*)(sm1 + A1_AH_OFF),
                      (const uint32_t*)(sm1 + A1_AL_OFF),
                      (const uint32_t*)(sm1 + s * A1_STG + A1_BH_OFF),
                      (const uint32_t*)(sm1 + s * A1_STG + A1_BL_OFF),
                      wm, wn, lane, acc);
        __syncthreads();
    }

    // ---- epilogue: relu + bf16 hi/lo split ----
#pragma unroll
    for (int i = 0; i < 4; ++i) {
#pragma unroll
        for (int j = 0; j < 4; ++j) {
            int cn = n0 + wn * 32 + j * 8 + 2 * (lane & 3);
            float2 bb = *(const float2*)(bias + cn);
            int rm = m0 + wm * 64 + i * 16 + (lane >> 2);
#pragma unroll
            for (int h = 0; h < 2; ++h) {
                int r = rm + h * 8;
                if (r < Mrows) {
                    float vx = fmaxf(acc[i][j][2 * h + 0] + bb.x, 0.f);
                    float vy = fmaxf(acc[i][j][2 * h + 1] + bb.y, 0.f);
                    size_t off = (size_t)r * Ncols + cn;
                    uint32_t lo;
                    uint32_t hi = pack_hi(vx, vy, lo);
                    *(uint32_t*)(Ch + off) = hi;
                    *(uint32_t*)(Cl + off) = lo;
                }
            }
        }
    }
}

// ---------------- GEMM2: bf16-pair A; fp32 + fp16(relu) epilogue ----------------
__device__ __forceinline__ void stage_load2(uint32_t smb, int s,
        const __nv_bfloat16* Ah, const __nv_bfloat16* Al,
        const __nv_bfloat16* Bh, const __nv_bfloat16* Bl,
        int m0, int n0, int k0, int Mrows, int Kdim, int tid)
{
    uint32_t base = smb + s * STG_B;
#pragma unroll
    for (int uu = 0; uu < 2; ++uu) {
        int u   = tid + uu * 256;
        int row = u >> 2, seg = u & 3;
        int m = m0 + row;
        if (m >= Mrows) m = Mrows - 1;
        size_t ao = (size_t)m * Kdim + k0 + seg * 8;
        size_t bo = (size_t)(n0 + row) * Kdim + k0 + seg * 8;
        uint32_t d = base + row * 80 + seg * 16;
        cpa16(d,             Ah + ao);
        cpa16(d + ARR_B,     Al + ao);
        cpa16(d + 2 * ARR_B, Bh + bo);
        cpa16(d + 3 * ARR_B, Bl + bo);
    }
}

__global__ void __launch_bounds__(256, 2)
k_gemm2(const __nv_bfloat16* __restrict__ Ah, const __nv_bfloat16* __restrict__ Al,
        const __nv_bfloat16* __restrict__ Bh, const __nv_bfloat16* __restrict__ Bl,
        const float* __restrict__ bias,
        float* __restrict__ Cf, __half* __restrict__ Cf16,
        int Mrows, int Ncols, int Kdim)
{
    extern __shared__ uint32_t sm[];
    const uint32_t smb = (uint32_t)__cvta_generic_to_shared(sm);

    const int tid  = threadIdx.x;
    const int wid  = tid >> 5;
    const int lane = tid & 31;
    const int wm   = wid >> 2;
    const int wn   = wid & 3;
    const int m0   = blockIdx.y * 128;
    const int n0   = blockIdx.x * 128;

    float acc[4][4][4];
#pragma unroll
    for (int i = 0; i < 4; ++i)
#pragma unroll
        for (int j = 0; j < 4; ++j)
#pragma unroll
            for (int r = 0; r < 4; ++r) acc[i][j][r] = 0.f;

    const int nc = Kdim >> 5;
    stage_load2(smb, 0, Ah, Al, Bh, Bl, m0, n0, 0, Mrows, Kdim, tid);
    cpa_commit();

    for (int c = 0; c < nc; ++c) {
        const int s = c & 1;
        if (c + 1 < nc) {
            stage_load2(smb, s ^ 1, Ah, Al, Bh, Bl, m0, n0, (c + 1) << 5, Mrows, Kdim, tid);
            cpa_commit();
            cpa_wait<1>();
        } else {
            cpa_wait<0>();
        }
        __syncthreads();
        const uint32_t* base = sm + s * (STG_B / 4);
        compute_stage(base, base + ARR_B / 4, base + 2 * (ARR_B / 4), base + 3 * (ARR_B / 4),
                      wm, wn, lane, acc);
        __syncthreads();
    }

#pragma unroll
    for (int i = 0; i < 4; ++i) {
#pragma unroll
        for (int j = 0; j < 4; ++j) {
            int cn = n0 + wn * 32 + j * 8 + 2 * (lane & 3);
            float2 bb = *(const float2*)(bias + cn);
            int rm = m0 + wm * 64 + i * 16 + (lane >> 2);
#pragma unroll
            for (int h = 0; h < 2; ++h) {
                int r = rm + h * 8;
                if (r < Mrows) {
                    float vx = acc[i][j][2 * h + 0] + bb.x;
                    float vy = acc[i][j][2 * h + 1] + bb.y;
                    size_t off = (size_t)r * Ncols + cn;
                    *(float2*)(Cf + off) = make_float2(vx, vy);
                    __half2 hv = __floats2half2_rn(fmaxf(vx, 0.f), fmaxf(vy, 0.f));
                    *(__half2*)(Cf16 + off) = hv;
                }
            }
        }
    }
}

// ---------------- fused propagation ----------------
__global__ void __launch_bounds__(256)
k_final(const float* __restrict__ gamma, float* __restrict__ out)
{
    int t = blockIdx.x * blockDim.x + threadIdx.x;
    if (t >= EE * (COUT / 4)) return;
    int e = t >> 6;
    int c = (t & 63) << 2;

    float4 hv = *(const float4*)(g_h + (size_t)e * COUT + c);
    float g0 = __ldg(gamma);
    float4 acc;
    acc.x = g0 * hv.x; acc.y = g0 * hv.y;
    acc.z = g0 * hv.z; acc.w = g0 * hv.w;

#pragma unroll
    for (int k = 0; k < KHOPS; ++k) {
        int   idx = g_idx[(size_t)k * EE + e];
        float w   = __ldg(gamma + k + 1) * g_P[(size_t)k * EE + e];
        uint2 raw = *(const uint2*)(g_hf + (size_t)idx * COUT + c);
        __half2 p0 = *(__half2*)&raw.x;
        __half2 p1 = *(__half2*)&raw.y;
        float2 f0 = __half22float2(p0);
        float2 f1 = __half22float2(p1);
        acc.x += w * f0.x;
        acc.y += w * f0.y;
        acc.z += w * f1.x;
        acc.w += w * f1.y;
    }
    *(float4*)(out + (size_t)e * COUT + c) = acc;
}

// ---------------- launch ----------------
extern "C" void kernel_launch(void* const* d_in, const int* in_sizes, int n_in,
                              void* d_out, int out_size)
{
    const float* x     = nullptr;
    const int*   ei    = nullptr;
    const float* W1    = nullptr;
    const float* b1    = nullptr;
    const float* W2    = nullptr;
    const float* b2    = nullptr;
    const float* gamma = nullptr;
    for (int i = 0; i < n_in; ++i) {
        switch (in_sizes[i]) {
            case 102400000: x     = (const float*)d_in[i]; break;
            case 400000:    ei    = (const int*)d_in[i];   break;
            case 262144:    W1    = (const float*)d_in[i]; break;
            case 512:       b1    = (const float*)d_in[i]; break;
            case 131072:    W2    = (const float*)d_in[i]; break;
            case 256:       b2    = (const float*)d_in[i]; break;
            case 11:        gamma = (const float*)d_in[i]; break;
        }
    }
    float* out = (float*)d_out;

    k_detect<<<1, 256>>>(ei);
    k_zero_deg<<<(NN + 255) / 256, 256>>>();
    k_count<<<(EE + 255) / 256, 256>>>(ei);
    k_coef<<<(EE + 255) / 256, 256>>>(ei);

    const int eb = (EE + 255) / 256;
    k_chain<<<eb, 256>>>();

    __nv_bfloat16 *w1h, *w1l, *w2h, *w2l, *t1h, *t1l;
    float *hbuf;
    __half *hfbuf;
    cudaGetSymbolAddress((void**)&w1h, g_W1h);
    cudaGetSymbolAddress((void**)&w1l, g_W1l);
    cudaGetSymbolAddress((void**)&w2h, g_W2h);
    cudaGetSymbolAddress((void**)&w2l, g_W2l);
    cudaGetSymbolAddress((void**)&t1h, g_t1h);
    cudaGetSymbolAddress((void**)&t1l, g_t1l);
    cudaGetSymbolAddress((void**)&hbuf, g_h);
    cudaGetSymbolAddress((void**)&hfbuf, g_hf);

    k_prep_w<<<(CIN * CHID + 255) / 256, 256>>>(W1, w1h, w1l, CIN, CHID);
    k_prep_w<<<(CHID * COUT + 255) / 256, 256>>>(W2, w2h, w2l, CHID, COUT);

    cudaFuncSetAttribute(k_gemm1, cudaFuncAttributeMaxDynamicSharedMemorySize, SMEM1);
    cudaFuncSetAttribute(k_gemm2, cudaFuncAttributeMaxDynamicSharedMemorySize, 2 * STG_B);

    const int mt = (CHUNK + 127) / 128;
    dim3 g1(CHID / 128, mt);
    dim3 g2(COUT / 128, mt);
    for (int row0 = 0; row0 < NN; row0 += CHUNK) {
        k_gemm1<<<g1, 256, SMEM1>>>(x + (size_t)row0 * CIN, w1h, w1l, b1,
                                    t1h, t1l, CHUNK, CHID, CIN);
        k_gemm2<<<g2, 256, 2 * STG_B>>>(t1h, t1l, w2h, w2l, b2,
                                        hbuf + (size_t)row0 * COUT,
                                        hfbuf + (size_t)row0 * COUT,
                                        CHUNK, COUT, CHID);
    }

    const int total = EE * (COUT / 4);
    k_final<<<(total + 255) / 256, 256>>>(gamma, out);
}